// round 2
// baseline (speedup 1.0000x reference)
#include <cuda_runtime.h>

#define B_   16
#define C_   384
#define H_   56
#define W_   56
#define HW_  3136
#define NHW_ 50176
#define TOT_ 19267584
#define KL   31
#define PL   15
#define KS   5
#define TS   86      // 56 + 2*15
#define VROWS 85     // vertical-pair rows: v[r] = (tile[r], tile[r+1]), r=0..84
#define VSTR  92     // stride in 8-byte elements; 2*VSTR % 16 == 8 -> conflict-free
#define NTHR  224    // 28 row-pairs x 8 strips of 7 cols

typedef unsigned long long ull;

// Scratch (allocation-free contract: __device__ globals)
__device__ float g_yl[TOT_];
__device__ float g_ys[TOT_];
__device__ float g_acc[C_ * 4];   // per channel: sumL, sqL, sumS, sqS
__device__ float g_prm[C_ * 3];   // per channel: aL, aS, bias

__device__ __forceinline__ ull pack2(float lo, float hi) {
    ull r; asm("mov.b64 %0, {%1, %2};" : "=l"(r) : "f"(lo), "f"(hi)); return r;
}
__device__ __forceinline__ void unpack2(ull v, float& lo, float& hi) {
    asm("mov.b64 {%0, %1}, %2;" : "=f"(lo), "=f"(hi) : "l"(v));
}
__device__ __forceinline__ ull fma2(ull a, ull b, ull c) {
    ull d; asm("fma.rn.f32x2 %0, %1, %2, %3;" : "=l"(d) : "l"(a), "l"(b), "l"(c)); return d;
}
__device__ __forceinline__ ull add2(ull a, ull b) {
    ull d; asm("add.rn.f32x2 %0, %1, %2;" : "=l"(d) : "l"(a), "l"(b)); return d;
}

__global__ void k_zero() {
    int i = blockIdx.x * blockDim.x + threadIdx.x;
    if (i < C_ * 4) g_acc[i] = 0.f;
}

// dynamic smem layout (in ull): v[VROWS*VSTR] | wp[961] | wsp[32] | red (floats)
#define V_ULL   (VROWS * VSTR)
#define WP_OFF  V_ULL
#define WSP_OFF (WP_OFF + 961)
#define RED_OFF (WSP_OFF + 32)
#define SMEM_ULL (RED_OFF + 16)
#define SMEM_BYTES (SMEM_ULL * 8)

__global__ __launch_bounds__(NTHR) void k_conv(const float* __restrict__ x,
                                               const float* __restrict__ wl_g,
                                               const float* __restrict__ ws_g) {
    extern __shared__ ull dsm[];
    ull* v   = dsm;
    ull* wp  = dsm + WP_OFF;
    ull* wsp = dsm + WSP_OFF;
    float* red = (float*)(dsm + RED_OFF);

    const int blk = blockIdx.x;          // n*C + c
    const int c   = blk % C_;
    const int tid = threadIdx.x;
    const float* img = x + (size_t)blk * HW_;

    // Build vertically-paired padded tile: v[r][col] = (tile[r][col], tile[r+1][col])
    // tile coords: row r corresponds to image row r-15, col-15 (zero halo).
    for (int idx = tid; idx < VROWS * TS; idx += NTHR) {
        int r = idx / TS, col = idx - r * TS;
        int hy0 = r - PL, wx = col - PL;
        float a = 0.f, b = 0.f;
        if (wx >= 0 && wx < W_) {
            if (hy0 >= 0 && hy0 < H_)       a = img[hy0 * W_ + wx];
            int hy1 = hy0 + 1;
            if (hy1 >= 0 && hy1 < H_)       b = img[hy1 * W_ + wx];
        }
        v[r * VSTR + col] = pack2(a, b);
    }
    // Packed weights (w, w)
    for (int idx = tid; idx < KL * KL; idx += NTHR) {
        float w = wl_g[c * KL * KL + idx];
        wp[idx] = pack2(w, w);
    }
    if (tid < KS * KS) {
        float w = ws_g[c * KS * KS + tid];
        wsp[tid] = pack2(w, w);
    }
    __syncthreads();

    const int strip = tid & 7;           // 0..7
    const int rp    = tid >> 3;          // 0..27
    const int col0  = strip * 7;
    const int h     = rp * 2;            // output rows h, h+1

    // ---- 31x31 depthwise conv, f32x2 over row pair, 7-wide rolling window ----
    ull accL[7];
    #pragma unroll
    for (int t = 0; t < 7; t++) accL[t] = 0ull;

    #pragma unroll 1
    for (int i = 0; i < KL; i++) {
        const ull* xr = &v[(h + i) * VSTR + col0];
        const ull* wr = &wp[i * KL];
        ull xw[7];
        #pragma unroll
        for (int t = 0; t < 7; t++) xw[t] = xr[t];
        #pragma unroll
        for (int j = 0; j < KL; j++) {
            const ull wv = wr[j];
            #pragma unroll
            for (int t = 0; t < 7; t++)
                accL[t] = fma2(xw[(j + t) % 7], wv, accL[t]);
            if (j < KL - 1) xw[j % 7] = xr[j + 7];
        }
    }

    // ---- 5x5 depthwise conv (pad 2): offset +13 in the 15-halo tile ----
    ull accS[7];
    #pragma unroll
    for (int t = 0; t < 7; t++) accS[t] = 0ull;
    #pragma unroll
    for (int i = 0; i < KS; i++) {
        const ull* xr = &v[(h + i + 13) * VSTR + col0 + 13];
        const ull* wr = &wsp[i * KS];
        ull xv[11];
        #pragma unroll
        for (int t = 0; t < 11; t++) xv[t] = xr[t];
        #pragma unroll
        for (int j = 0; j < KS; j++) {
            const ull wv = wr[j];
            #pragma unroll
            for (int t = 0; t < 7; t++)
                accS[t] = fma2(xv[j + t], wv, accS[t]);
        }
    }

    // ---- store + per-thread stats (packed) ----
    ull sL2 = 0ull, qL2 = 0ull, sS2 = 0ull, qS2 = 0ull;
    const size_t ob = (size_t)blk * HW_ + (size_t)h * W_ + col0;
    #pragma unroll
    for (int t = 0; t < 7; t++) {
        float l0, l1, s0, s1;
        unpack2(accL[t], l0, l1);
        unpack2(accS[t], s0, s1);
        g_yl[ob + t]       = l0;
        g_yl[ob + W_ + t]  = l1;
        g_ys[ob + t]       = s0;
        g_ys[ob + W_ + t]  = s1;
        sL2 = add2(sL2, accL[t]); qL2 = fma2(accL[t], accL[t], qL2);
        sS2 = add2(sS2, accS[t]); qS2 = fma2(accS[t], accS[t], qS2);
    }
    float a0, a1;
    unpack2(sL2, a0, a1); float sL = a0 + a1;
    unpack2(qL2, a0, a1); float qL = a0 + a1;
    unpack2(sS2, a0, a1); float sS = a0 + a1;
    unpack2(qS2, a0, a1); float qS = a0 + a1;

    // ---- block reduction of the 4 stats (7 warps) ----
    #pragma unroll
    for (int o = 16; o; o >>= 1) {
        sL += __shfl_down_sync(0xffffffffu, sL, o);
        qL += __shfl_down_sync(0xffffffffu, qL, o);
        sS += __shfl_down_sync(0xffffffffu, sS, o);
        qS += __shfl_down_sync(0xffffffffu, qS, o);
    }
    const int lane = tid & 31, wpid = tid >> 5;
    if (lane == 0) { red[wpid*4+0]=sL; red[wpid*4+1]=qL; red[wpid*4+2]=sS; red[wpid*4+3]=qS; }
    __syncthreads();
    if (tid < 4) {
        float vv = 0.f;
        #pragma unroll
        for (int ww = 0; ww < 7; ww++) vv += red[ww * 4 + tid];
        atomicAdd(&g_acc[c * 4 + tid], vv);
    }
}

__global__ void k_stats(const float* __restrict__ gL, const float* __restrict__ bL,
                        const float* __restrict__ gS, const float* __restrict__ bS) {
    int c = blockIdx.x * blockDim.x + threadIdx.x;
    if (c >= C_) return;
    const float inv_n = 1.f / (float)NHW_;
    float mL = g_acc[c*4+0] * inv_n;
    float vL = g_acc[c*4+1] * inv_n - mL * mL;
    float aL = gL[c] * rsqrtf(vL + 1e-5f);
    float mS = g_acc[c*4+2] * inv_n;
    float vS = g_acc[c*4+3] * inv_n - mS * mS;
    float aS = gS[c] * rsqrtf(vS + 1e-5f);
    g_prm[c]        = aL;
    g_prm[C_ + c]   = aS;
    g_prm[2*C_ + c] = bL[c] - mL * aL + bS[c] - mS * aS;
}

__global__ __launch_bounds__(256) void k_out(float* __restrict__ out) {
    int i = blockIdx.x * blockDim.x + threadIdx.x;
    if (i >= TOT_ / 4) return;
    int e = i * 4;
    int c = (e / HW_) % C_;          // HW_ divisible by 4 -> channel constant in float4
    float aL = g_prm[c], aS = g_prm[C_ + c], bb = g_prm[2*C_ + c];
    float4 l = ((const float4*)g_yl)[i];
    float4 s = ((const float4*)g_ys)[i];
    float4 o;
    o.x = fmaf(aL, l.x, fmaf(aS, s.x, bb));
    o.y = fmaf(aL, l.y, fmaf(aS, s.y, bb));
    o.z = fmaf(aL, l.z, fmaf(aS, s.z, bb));
    o.w = fmaf(aL, l.w, fmaf(aS, s.w, bb));
    ((float4*)out)[i] = o;
}

extern "C" void kernel_launch(void* const* d_in, const int* in_sizes, int n_in,
                              void* d_out, int out_size) {
    const float* x  = (const float*)d_in[0];
    const float* wl = (const float*)d_in[1];
    const float* gl = (const float*)d_in[2];
    const float* bl = (const float*)d_in[3];
    const float* ws = (const float*)d_in[4];
    const float* gs = (const float*)d_in[5];
    const float* bs = (const float*)d_in[6];

    cudaFuncSetAttribute(k_conv, cudaFuncAttributeMaxDynamicSharedMemorySize, SMEM_BYTES);

    k_zero<<<6, 256>>>();
    k_conv<<<B_ * C_, NTHR, SMEM_BYTES>>>(x, wl, ws);
    k_stats<<<2, 192>>>(gl, bl, gs, bs);
    k_out<<<(TOT_ / 4 + 255) / 256, 256>>>((float*)d_out);
}

// round 5
// speedup vs baseline: 1.1790x; 1.1790x over previous
#include <cuda_runtime.h>

#define B_   16
#define C_   384
#define H_   56
#define W_   56
#define HW_  3136
#define NHW_ 50176
#define TOT_ 19267584
#define KL   31
#define PL   15
#define KS   5
#define TS   86      // 56 + 2*15
#define STR  87      // odd stride: 32 consecutive rows -> 32 distinct banks
#define WIDE 28      // output columns per thread
#define NWORK 112    // 56 rows x 2 strips
#define NTHR 128     // padded to 4 warps

// Scratch (allocation-free contract: __device__ globals)
__device__ float g_yl[TOT_];
__device__ float g_ys[TOT_];
__device__ float g_acc[C_ * 4];   // per channel: sumL, sqL, sumS, sqS
__device__ float g_prm[C_ * 3];   // per channel: aL, aS, bias

__global__ void k_zero() {
    int i = blockIdx.x * blockDim.x + threadIdx.x;
    if (i < C_ * 4) g_acc[i] = 0.f;
}

__global__ __launch_bounds__(NTHR) void k_conv(const float* __restrict__ x,
                                               const float* __restrict__ wl_g,
                                               const float* __restrict__ ws_g) {
    __shared__ float tile[TS * STR];
    __shared__ float wl[KL * KL];
    __shared__ float ws[KS * KS];
    __shared__ float red[4 * 4];

    const int blk = blockIdx.x;          // n*C + c
    const int c   = blk % C_;
    const int tid = threadIdx.x;
    const float* img = x + (size_t)blk * HW_;

    // Load padded tile (zero halo of 15), row stride 87
    for (int idx = tid; idx < TS * TS; idx += NTHR) {
        int r = idx / TS, q = idx - r * TS;
        int hy = r - PL, wx = q - PL;
        float v = 0.f;
        if (hy >= 0 && hy < H_ && wx >= 0 && wx < W_) v = img[hy * W_ + wx];
        tile[r * STR + q] = v;
    }
    for (int idx = tid; idx < KL * KL; idx += NTHR) wl[idx] = wl_g[c * KL * KL + idx];
    if (tid < KS * KS) ws[tid] = ws_g[c * KS * KS + tid];
    __syncthreads();

    float sL = 0.f, qL = 0.f, sS = 0.f, qS = 0.f;

    if (tid < NWORK) {
        const int row  = tid % 56;           // output row
        const int col0 = (tid / 56) * WIDE;  // 0 or 28

        // ---- 31x31 depthwise conv, 28-wide rolling register window ----
        float accL[WIDE];
        #pragma unroll
        for (int t = 0; t < WIDE; t++) accL[t] = 0.f;

        #pragma unroll 1
        for (int i = 0; i < KL; i++) {
            const float* xr = &tile[(row + i) * STR + col0];
            const float* wr = &wl[i * KL];
            float xw[WIDE];
            #pragma unroll
            for (int t = 0; t < WIDE; t++) xw[t] = xr[t];
            #pragma unroll
            for (int j = 0; j < KL; j++) {
                const float wv = wr[j];
                #pragma unroll
                for (int t = 0; t < WIDE; t++)
                    accL[t] = fmaf(xw[(j + t) % WIDE], wv, accL[t]);
                if (j < KL - 1) xw[j % WIDE] = xr[j + WIDE];
            }
        }

        // ---- 5x5 depthwise conv (pad 2): offset +13 in the 15-halo tile ----
        float accS[WIDE];
        #pragma unroll
        for (int t = 0; t < WIDE; t++) accS[t] = 0.f;
        #pragma unroll 1
        for (int i = 0; i < KS; i++) {
            const float* xr = &tile[(row + i + 13) * STR + col0 + 13];
            const float* wr = &ws[i * KS];
            float xv[WIDE + 4];
            #pragma unroll
            for (int t = 0; t < WIDE + 4; t++) xv[t] = xr[t];
            #pragma unroll
            for (int j = 0; j < KS; j++) {
                const float wv = wr[j];
                #pragma unroll
                for (int t = 0; t < WIDE; t++)
                    accS[t] = fmaf(xv[j + t], wv, accS[t]);
            }
        }

        // ---- vectorized stores + per-thread stats ----
        const size_t ob = (size_t)blk * HW_ + (size_t)row * W_ + col0;
        #pragma unroll
        for (int t = 0; t < WIDE; t += 4) {
            float4 l = make_float4(accL[t], accL[t+1], accL[t+2], accL[t+3]);
            float4 s = make_float4(accS[t], accS[t+1], accS[t+2], accS[t+3]);
            *(float4*)&g_yl[ob + t] = l;
            *(float4*)&g_ys[ob + t] = s;
        }
        #pragma unroll
        for (int t = 0; t < WIDE; t++) {
            sL += accL[t]; qL = fmaf(accL[t], accL[t], qL);
            sS += accS[t]; qS = fmaf(accS[t], accS[t], qS);
        }
    }

    // ---- block reduction of the 4 stats (4 warps, padded threads carry zeros) ----
    #pragma unroll
    for (int o = 16; o; o >>= 1) {
        sL += __shfl_down_sync(0xffffffffu, sL, o);
        qL += __shfl_down_sync(0xffffffffu, qL, o);
        sS += __shfl_down_sync(0xffffffffu, sS, o);
        qS += __shfl_down_sync(0xffffffffu, qS, o);
    }
    const int lane = tid & 31, wpid = tid >> 5;
    if (lane == 0) { red[wpid*4+0]=sL; red[wpid*4+1]=qL; red[wpid*4+2]=sS; red[wpid*4+3]=qS; }
    __syncthreads();
    if (tid < 4) {
        float v = 0.f;
        #pragma unroll
        for (int ww = 0; ww < 4; ww++) v += red[ww * 4 + tid];
        atomicAdd(&g_acc[c * 4 + tid], v);
    }
}

__global__ void k_stats(const float* __restrict__ gL, const float* __restrict__ bL,
                        const float* __restrict__ gS, const float* __restrict__ bS) {
    int c = blockIdx.x * blockDim.x + threadIdx.x;
    if (c >= C_) return;
    const float inv_n = 1.f / (float)NHW_;
    float mL = g_acc[c*4+0] * inv_n;
    float vL = g_acc[c*4+1] * inv_n - mL * mL;
    float aL = gL[c] * rsqrtf(vL + 1e-5f);
    float mS = g_acc[c*4+2] * inv_n;
    float vS = g_acc[c*4+3] * inv_n - mS * mS;
    float aS = gS[c] * rsqrtf(vS + 1e-5f);
    g_prm[c]        = aL;
    g_prm[C_ + c]   = aS;
    g_prm[2*C_ + c] = bL[c] - mL * aL + bS[c] - mS * aS;
}

__global__ __launch_bounds__(256) void k_out(float* __restrict__ out) {
    int i = blockIdx.x * blockDim.x + threadIdx.x;
    if (i >= TOT_ / 4) return;
    int e = i * 4;
    int c = (e / HW_) % C_;          // HW_ divisible by 4 -> channel constant in float4
    float aL = g_prm[c], aS = g_prm[C_ + c], bb = g_prm[2*C_ + c];
    float4 l = ((const float4*)g_yl)[i];
    float4 s = ((const float4*)g_ys)[i];
    float4 o;
    o.x = fmaf(aL, l.x, fmaf(aS, s.x, bb));
    o.y = fmaf(aL, l.y, fmaf(aS, s.y, bb));
    o.z = fmaf(aL, l.z, fmaf(aS, s.z, bb));
    o.w = fmaf(aL, l.w, fmaf(aS, s.w, bb));
    ((float4*)out)[i] = o;
}

extern "C" void kernel_launch(void* const* d_in, const int* in_sizes, int n_in,
                              void* d_out, int out_size) {
    const float* x  = (const float*)d_in[0];
    const float* wl = (const float*)d_in[1];
    const float* gl = (const float*)d_in[2];
    const float* bl = (const float*)d_in[3];
    const float* ws = (const float*)d_in[4];
    const float* gs = (const float*)d_in[5];
    const float* bs = (const float*)d_in[6];

    k_zero<<<6, 256>>>();
    k_conv<<<B_ * C_, NTHR>>>(x, wl, ws);
    k_stats<<<2, 192>>>(gl, bl, gs, bs);
    k_out<<<(TOT_ / 4 + 255) / 256, 256>>>((float*)d_out);
}